// round 3
// baseline (speedup 1.0000x reference)
#include <cuda_runtime.h>
#include <cuda_bf16.h>
#include <math.h>
#include <stdint.h>

// ---------------------------------------------------------------------------
// Problem constants
// ---------------------------------------------------------------------------
#define NUM_HEADS   8
#define NUM_CHUNKS  50000
#define INPUT_DIM   768
#define HIDDEN_DIM  512
#define OUTPUT_DIM  256
#define NUM_CELLS   2048
#define MAX_LEN     64
#define HEAD_DIM    64   // HIDDEN_DIM / NUM_HEADS
#define QKV_DIM     1536 // 3 * HIDDEN_DIM

// ---------------------------------------------------------------------------
// Scratch (device globals -- allocation-free contract). 256B aligned so
// float4 paths are safe.
// ---------------------------------------------------------------------------
__device__ __align__(256) float g_Weff[QKV_DIM * INPUT_DIM];         // [1536,768]
__device__ __align__(256) float g_beff[QKV_DIM];                     // [1536]
__device__ __align__(256) float g_QKV[(size_t)NUM_CHUNKS * QKV_DIM]; // [50000,1536]
__device__ __align__(256) float g_pooled[NUM_CELLS * HIDDEN_DIM];    // [2048,512]
__device__ __align__(256) float g_Wfinal[OUTPUT_DIM * HIDDEN_DIM];   // [256,512]
__device__ __align__(256) float g_bfinal[OUTPUT_DIM];                // [256]
__device__ int g_idx_is64;   // 1 if cell_idx is int64, 0 if int32
__device__ int g_len_is64;   // 1 if cell_len is int64, 0 if int32

// ---------------------------------------------------------------------------
// Dtype detection: JAX default config downcasts int64 -> int32. If the arrays
// really are int64 (values < 2^31), every odd 32-bit word is zero; if int32,
// the OR of 256 random odd words is nonzero with overwhelming probability.
// ---------------------------------------------------------------------------
__global__ void detect_dtype_kernel(const int* __restrict__ idx_words,
                                    const int* __restrict__ len_words)
{
    if (threadIdx.x == 0 && blockIdx.x == 0) {
        int oi = 0, ol = 0;
        for (int i = 0; i < 256; i++) oi |= idx_words[2 * i + 1];
        for (int i = 0; i < 256; i++) ol |= len_words[2 * i + 1];
        g_idx_is64 = (oi == 0) ? 1 : 0;
        g_len_is64 = (ol == 0) ? 1 : 0;
    }
}

// ---------------------------------------------------------------------------
// Generic tiled SGEMM:  C[M,N] = A[M,K] * op(B) (+ bias[N])
//   BT=true : B is [N,K] row-major (C = A * B^T)
//   BT=false: B is [K,N] row-major (C = A * B)
// K % 8 == 0, N % 128 == 0 at all call sites; M may be ragged (guarded).
// 128x128x8 tile, 256 threads, 8x8 micro-tile per thread.
// ---------------------------------------------------------------------------
template <bool BT>
__global__ void __launch_bounds__(256)
sgemm_kernel(int M, int N, int K,
             const float* __restrict__ A,
             const float* __restrict__ B,
             const float* __restrict__ bias,
             float* __restrict__ C)
{
    __shared__ float As[8][128];
    __shared__ float Bs[8][128];

    const int tid = threadIdx.x;
    const int bm = blockIdx.y * 128;
    const int bn = blockIdx.x * 128;

    const int tx = tid & 15;   // output column group
    const int ty = tid >> 4;   // output row group

    float acc[8][8];
#pragma unroll
    for (int i = 0; i < 8; i++)
#pragma unroll
        for (int j = 0; j < 8; j++) acc[i][j] = 0.f;

    const int arow = tid >> 1;        // 0..127
    const int ak   = (tid & 1) * 4;   // 0 or 4
    const int bkr  = tid >> 5;        // 0..7   (NN path)
    const int bnc  = (tid & 31) * 4;  // 0..124 (NN path)

    for (int k0 = 0; k0 < K; k0 += 8) {
        float4 av = make_float4(0.f, 0.f, 0.f, 0.f);
        if (bm + arow < M)
            av = *(const float4*)(A + (size_t)(bm + arow) * K + k0 + ak);
        As[ak + 0][arow] = av.x;
        As[ak + 1][arow] = av.y;
        As[ak + 2][arow] = av.z;
        As[ak + 3][arow] = av.w;

        if (BT) {
            float4 bv = make_float4(0.f, 0.f, 0.f, 0.f);
            if (bn + arow < N)
                bv = *(const float4*)(B + (size_t)(bn + arow) * K + k0 + ak);
            Bs[ak + 0][arow] = bv.x;
            Bs[ak + 1][arow] = bv.y;
            Bs[ak + 2][arow] = bv.z;
            Bs[ak + 3][arow] = bv.w;
        } else {
            float4 bv = *(const float4*)(B + (size_t)(k0 + bkr) * N + bn + bnc);
            *(float4*)&Bs[bkr][bnc] = bv;
        }
        __syncthreads();

#pragma unroll
        for (int kk = 0; kk < 8; kk++) {
            float a[8], b[8];
            *(float4*)&a[0] = *(const float4*)&As[kk][ty * 8];
            *(float4*)&a[4] = *(const float4*)&As[kk][ty * 8 + 4];
            *(float4*)&b[0] = *(const float4*)&Bs[kk][tx * 8];
            *(float4*)&b[4] = *(const float4*)&Bs[kk][tx * 8 + 4];
#pragma unroll
            for (int i = 0; i < 8; i++)
#pragma unroll
                for (int j = 0; j < 8; j++)
                    acc[i][j] = fmaf(a[i], b[j], acc[i][j]);
        }
        __syncthreads();
    }

#pragma unroll
    for (int i = 0; i < 8; i++) {
        int row = bm + ty * 8 + i;
        if (row < M) {
#pragma unroll
            for (int j = 0; j < 8; j += 4) {
                int col = bn + tx * 8 + j;
                float4 o;
                o.x = acc[i][j + 0] + (bias ? bias[col + 0] : 0.f);
                o.y = acc[i][j + 1] + (bias ? bias[col + 1] : 0.f);
                o.z = acc[i][j + 2] + (bias ? bias[col + 2] : 0.f);
                o.w = acc[i][j + 3] + (bias ? bias[col + 3] : 0.f);
                *(float4*)(C + (size_t)row * N + col) = o;
            }
        }
    }
}

// ---------------------------------------------------------------------------
// Combined biases: beff = Wi{q,k,v}@b{q,k,v} + b_in ; bfinal = Wout@bo + bout
// ---------------------------------------------------------------------------
__global__ void combine_bias_kernel(const float* __restrict__ W_in,
                                    const float* __restrict__ b_in,
                                    const float* __restrict__ bq,
                                    const float* __restrict__ bk,
                                    const float* __restrict__ bv,
                                    const float* __restrict__ Wout,
                                    const float* __restrict__ bo,
                                    const float* __restrict__ bout,
                                    float* __restrict__ beff,
                                    float* __restrict__ bfinal)
{
    int i = blockIdx.x * blockDim.x + threadIdx.x;
    if (i < QKV_DIM) {
        const float* bsrc = (i < HIDDEN_DIM) ? bq : (i < 2 * HIDDEN_DIM ? bk : bv);
        const float* w = W_in + (size_t)i * HIDDEN_DIM;
        float s = 0.f;
        for (int k = 0; k < HIDDEN_DIM; k++) s = fmaf(w[k], bsrc[k], s);
        beff[i] = s + b_in[i];
    } else if (i < QKV_DIM + OUTPUT_DIM) {
        int o = i - QKV_DIM;
        const float* w = Wout + (size_t)o * HIDDEN_DIM;
        float s = 0.f;
        for (int k = 0; k < HIDDEN_DIM; k++) s = fmaf(w[k], bo[k], s);
        bfinal[o] = s + bout[o];
    }
}

// ---------------------------------------------------------------------------
// Attention + masked mean pool, fused. One block = (cell, head), 256 threads.
// pooled[c, h*64+d] = sum_m ( mean_{l<Leff} softmax_m(q_l.k_m/8) ) * v_m[d]
// ---------------------------------------------------------------------------
__global__ void __launch_bounds__(256)
attn_pool_kernel(const float* __restrict__ QKV,
                 const void* __restrict__ cell_idx,
                 const void* __restrict__ cell_len,
                 float* __restrict__ pooled)
{
    __shared__ float qs[64][66];   // Q tile; reused for attention probabilities
    __shared__ float ks[64][66];   // K tile
    __shared__ float wsum[64];     // column-mean attention weights
    __shared__ float part[4][64];  // partial pooled sums
    __shared__ int   ridx[64];     // gathered chunk row indices

    const int c = blockIdx.x;
    const int h = blockIdx.y;
    const int tid = threadIdx.x;
    const int hoff = h * HEAD_DIM;

    // dtype-agnostic index/length reads (low 32-bit word of each element)
    const int sI = g_idx_is64 ? 2 : 1;
    const int sL = g_len_is64 ? 2 : 1;
    const int* idx32 = (const int*)cell_idx;
    const int* len32 = (const int*)cell_len;

    int len = len32[(size_t)c * sL];
    int Leff = len < 1 ? 1 : (len > 64 ? 64 : len);

    if (tid < 64) ridx[tid] = idx32[((size_t)c * MAX_LEN + tid) * sI];
    __syncthreads();

    // Load Q,K rows (zero-fill rows >= Leff)
    for (int e = tid; e < 64 * 16; e += 256) {
        int l = e >> 4;
        int d4 = (e & 15) << 2;
        float4 qv = make_float4(0.f, 0.f, 0.f, 0.f);
        float4 kv = make_float4(0.f, 0.f, 0.f, 0.f);
        if (l < Leff) {
            size_t base = (size_t)ridx[l] * QKV_DIM + hoff + d4;
            qv = *(const float4*)(QKV + base);
            kv = *(const float4*)(QKV + base + HIDDEN_DIM);
        }
        qs[l][d4 + 0] = qv.x; qs[l][d4 + 1] = qv.y; qs[l][d4 + 2] = qv.z; qs[l][d4 + 3] = qv.w;
        ks[l][d4 + 0] = kv.x; ks[l][d4 + 1] = kv.y; ks[l][d4 + 2] = kv.z; ks[l][d4 + 3] = kv.w;
    }
    __syncthreads();

    // Scores + masked softmax. Thread (l = tid/4, g = tid%4) owns 16 key cols.
    const int l = tid >> 2;
    const int g = tid & 3;
    float p[16];
    float rmax = -1e30f;
#pragma unroll
    for (int j = 0; j < 16; j++) {
        int m = g * 16 + j;
        float acc = 0.f;
#pragma unroll
        for (int d = 0; d < 64; d++) acc = fmaf(qs[l][d], ks[m][d], acc);
        float s = (m < Leff) ? acc * 0.125f : -1e30f;  // 1/sqrt(64)
        p[j] = s;
        rmax = fmaxf(rmax, s);
    }
    rmax = fmaxf(rmax, __shfl_xor_sync(0xffffffffu, rmax, 1));
    rmax = fmaxf(rmax, __shfl_xor_sync(0xffffffffu, rmax, 2));

    float rsum = 0.f;
#pragma unroll
    for (int j = 0; j < 16; j++) {
        int m = g * 16 + j;
        float e = (m < Leff) ? __expf(p[j] - rmax) : 0.f;
        p[j] = e;
        rsum += e;
    }
    rsum += __shfl_xor_sync(0xffffffffu, rsum, 1);
    rsum += __shfl_xor_sync(0xffffffffu, rsum, 2);
    float inv = 1.f / rsum;

    __syncthreads();  // done reading qs -> safe to overwrite with probs
    if (l < Leff) {
#pragma unroll
        for (int j = 0; j < 16; j++) qs[l][g * 16 + j] = p[j] * inv;
    }
    __syncthreads();

    // Column mean over valid query rows -> per-key pooled attention weight
    if (tid < 64) {
        float s = 0.f;
        for (int ll = 0; ll < Leff; ll++) s += qs[ll][tid];
        wsum[tid] = s / (float)Leff;
    }
    __syncthreads();

    // pooled[d] = sum_{m<Leff} wsum[m] * V[m][d]
    const int pt = tid >> 6;   // 0..3
    const int d  = tid & 63;
    float acc = 0.f;
    for (int m = pt; m < Leff; m += 4)
        acc = fmaf(wsum[m], QKV[(size_t)ridx[m] * QKV_DIM + 2 * HIDDEN_DIM + hoff + d], acc);
    part[pt][d] = acc;
    __syncthreads();
    if (tid < 64)
        pooled[(size_t)c * HIDDEN_DIM + hoff + tid] =
            part[0][tid] + part[1][tid] + part[2][tid] + part[3][tid];
}

// ---------------------------------------------------------------------------
// Launch
// ---------------------------------------------------------------------------
extern "C" void kernel_launch(void* const* d_in, const int* in_sizes, int n_in,
                              void* d_out, int out_size)
{
    const float* chunk = (const float*)d_in[0];
    const float* Wq    = (const float*)d_in[1];
    const float* bq    = (const float*)d_in[2];
    const float* Wk    = (const float*)d_in[3];
    const float* bk    = (const float*)d_in[4];
    const float* Wv    = (const float*)d_in[5];
    const float* bv    = (const float*)d_in[6];
    const float* W_in  = (const float*)d_in[7];
    const float* b_in  = (const float*)d_in[8];
    const float* Wo    = (const float*)d_in[9];
    const float* bo    = (const float*)d_in[10];
    const float* Wout  = (const float*)d_in[11];
    const float* bout  = (const float*)d_in[12];
    const void*  cidx  = d_in[13];
    const void*  clen  = d_in[14];
    float* out = (float*)d_out;

    float *pWeff, *pbeff, *pQKV, *pPooled, *pWfinal, *pbfinal;
    cudaGetSymbolAddress((void**)&pWeff,   g_Weff);
    cudaGetSymbolAddress((void**)&pbeff,   g_beff);
    cudaGetSymbolAddress((void**)&pQKV,    g_QKV);
    cudaGetSymbolAddress((void**)&pPooled, g_pooled);
    cudaGetSymbolAddress((void**)&pWfinal, g_Wfinal);
    cudaGetSymbolAddress((void**)&pbfinal, g_bfinal);

    // 0) detect int32 vs int64 layout of cell_idx / cell_len
    detect_dtype_kernel<<<1, 32>>>((const int*)cidx, (const int*)clen);

    // 1) combined biases
    combine_bias_kernel<<<(QKV_DIM + OUTPUT_DIM + 255) / 256, 256>>>(
        W_in, b_in, bq, bk, bv, Wout, bo, bout, pbeff, pbfinal);

    // 2) combined projection weights: Weff[t*512+j,:] = W_in[t*512+j,:] @ W_t
    {
        dim3 grid(INPUT_DIM / 128, HIDDEN_DIM / 128);
        const float* Bs[3] = {Wq, Wk, Wv};
        for (int t = 0; t < 3; t++) {
            sgemm_kernel<false><<<grid, 256>>>(
                HIDDEN_DIM, INPUT_DIM, HIDDEN_DIM,
                W_in + (size_t)t * HIDDEN_DIM * HIDDEN_DIM,
                Bs[t], nullptr,
                pWeff + (size_t)t * HIDDEN_DIM * INPUT_DIM);
        }
    }

    // 3) Wfinal = Wout @ Wo
    {
        dim3 grid(HIDDEN_DIM / 128, OUTPUT_DIM / 128);
        sgemm_kernel<false><<<grid, 256>>>(
            OUTPUT_DIM, HIDDEN_DIM, HIDDEN_DIM, Wout, Wo, nullptr, pWfinal);
    }

    // 4) QKV projection over all unique chunks (NT GEMM, dominant cost)
    {
        dim3 grid(QKV_DIM / 128, (NUM_CHUNKS + 127) / 128);
        sgemm_kernel<true><<<grid, 256>>>(
            NUM_CHUNKS, QKV_DIM, INPUT_DIM, chunk, pWeff, pbeff, pQKV);
    }

    // 5) fused attention + masked mean pool
    {
        dim3 grid(NUM_CELLS, NUM_HEADS);
        attn_pool_kernel<<<grid, 256>>>(pQKV, cidx, clen, pPooled);
    }

    // 6) final projection: out = pooled @ Wfinal^T + bfinal
    {
        dim3 grid(OUTPUT_DIM / 128, NUM_CELLS / 128);
        sgemm_kernel<true><<<grid, 256>>>(
            NUM_CELLS, OUTPUT_DIM, HIDDEN_DIM, pPooled, pWfinal, pbfinal, out);
    }
}

// round 5
// speedup vs baseline: 1.0109x; 1.0109x over previous
#include <cuda_runtime.h>
#include <cuda_bf16.h>
#include <math.h>
#include <stdint.h>

// ---------------------------------------------------------------------------
// Problem constants
// ---------------------------------------------------------------------------
#define NUM_HEADS   8
#define NUM_CHUNKS  50000
#define INPUT_DIM   768
#define HIDDEN_DIM  512
#define OUTPUT_DIM  256
#define NUM_CELLS   2048
#define MAX_LEN     64
#define HEAD_DIM    64
#define QKV_DIM     1536
#define M_PAD       50048              // 391 * 128
#define SPLITK      4

// mma GEMM geometry
#define CHUNK_K     32                 // bf16 k per stage
#define NCHUNKS     72                 // 3 split phases * (768/32)
#define ROWB        80                 // padded smem row stride (bytes) for 32 bf16
#define TILE_BYTES  (128 * ROWB)       // 10240 per operand tile
#define STAGE_B     (2 * TILE_BYTES)   // 20480
#define SMEM_MMA    (3 * STAGE_B)      // 61440

// ---------------------------------------------------------------------------
// Device-global scratch (allocation-free contract)
// ---------------------------------------------------------------------------
__device__ __align__(1024) __nv_bfloat16 g_Ahi[(size_t)M_PAD * INPUT_DIM];
__device__ __align__(1024) __nv_bfloat16 g_Alo[(size_t)M_PAD * INPUT_DIM];
__device__ __align__(1024) __nv_bfloat16 g_Bhi[QKV_DIM * INPUT_DIM];
__device__ __align__(1024) __nv_bfloat16 g_Blo[QKV_DIM * INPUT_DIM];
__device__ __align__(256) float g_QKV[(size_t)NUM_CHUNKS * QKV_DIM];
__device__ __align__(256) float g_beff[QKV_DIM];
__device__ __align__(256) float g_pooled[NUM_CELLS * HIDDEN_DIM];
__device__ __align__(256) float g_Wfinal[OUTPUT_DIM * HIDDEN_DIM];
__device__ __align__(256) float g_bfinal[OUTPUT_DIM];
__device__ __align__(256) float g_WeffPart[SPLITK * QKV_DIM * INPUT_DIM];
__device__ __align__(256) float g_WfinalPart[SPLITK * OUTPUT_DIM * HIDDEN_DIM];
__device__ __align__(256) float g_outPart[SPLITK * NUM_CELLS * OUTPUT_DIM];
__device__ int g_idx_is64;
__device__ int g_len_is64;

// ---------------------------------------------------------------------------
// PTX helpers (all plain-sm_80-level: safe for non-'a' ptx target)
// ---------------------------------------------------------------------------
__device__ __forceinline__ uint32_t smem_u32(const void* p) {
    uint32_t a;
    asm("{ .reg .u64 t; cvta.to.shared.u64 t, %1; cvt.u32.u64 %0, t; }"
        : "=r"(a) : "l"(p));
    return a;
}
__device__ __forceinline__ void cp16(uint32_t d, const void* s) {
    asm volatile("cp.async.cg.shared.global [%0], [%1], 16;" :: "r"(d), "l"(s));
}
__device__ __forceinline__ void cp_commit() {
    asm volatile("cp.async.commit_group;" ::: "memory");
}
template <int N>
__device__ __forceinline__ void cp_wait() {
    asm volatile("cp.async.wait_group %0;" :: "n"(N) : "memory");
}
__device__ __forceinline__ void ldsm4(uint32_t& r0, uint32_t& r1, uint32_t& r2,
                                      uint32_t& r3, uint32_t a) {
    asm volatile("ldmatrix.sync.aligned.m8n8.x4.shared.b16 {%0,%1,%2,%3}, [%4];"
                 : "=r"(r0), "=r"(r1), "=r"(r2), "=r"(r3) : "r"(a));
}
__device__ __forceinline__ void mma16816(float* c, uint32_t a0, uint32_t a1,
                                         uint32_t a2, uint32_t a3,
                                         uint32_t b0, uint32_t b1) {
    asm volatile("mma.sync.aligned.m16n8k16.row.col.f32.bf16.bf16.f32 "
                 "{%0,%1,%2,%3}, {%4,%5,%6,%7}, {%8,%9}, {%0,%1,%2,%3};"
                 : "+f"(c[0]), "+f"(c[1]), "+f"(c[2]), "+f"(c[3])
                 : "r"(a0), "r"(a1), "r"(a2), "r"(a3), "r"(b0), "r"(b1));
}

// ---------------------------------------------------------------------------
// dtype detection (int64 vs silently-downcast int32 indices)
// ---------------------------------------------------------------------------
__global__ void detect_dtype_kernel(const int* __restrict__ iw, const int* __restrict__ lw) {
    if (threadIdx.x == 0 && blockIdx.x == 0) {
        int oi = 0, ol = 0;
        for (int i = 0; i < 256; i++) oi |= iw[2 * i + 1];
        for (int i = 0; i < 256; i++) ol |= lw[2 * i + 1];
        g_idx_is64 = (oi == 0) ? 1 : 0;
        g_len_is64 = (ol == 0) ? 1 : 0;
    }
}

// ---------------------------------------------------------------------------
// Combined biases
// ---------------------------------------------------------------------------
__global__ void combine_bias_kernel(const float* __restrict__ W_in, const float* __restrict__ b_in,
                                    const float* __restrict__ bq, const float* __restrict__ bk,
                                    const float* __restrict__ bv, const float* __restrict__ Wout,
                                    const float* __restrict__ bo, const float* __restrict__ bout,
                                    float* __restrict__ beff, float* __restrict__ bfinal) {
    int i = blockIdx.x * blockDim.x + threadIdx.x;
    if (i < QKV_DIM) {
        const float* bs = (i < HIDDEN_DIM) ? bq : (i < 2 * HIDDEN_DIM ? bk : bv);
        const float* w = W_in + (size_t)i * HIDDEN_DIM;
        float s = 0.f;
        for (int k = 0; k < HIDDEN_DIM; k++) s = fmaf(w[k], bs[k], s);
        beff[i] = s + b_in[i];
    } else if (i < QKV_DIM + OUTPUT_DIM) {
        int o = i - QKV_DIM;
        const float* w = Wout + (size_t)o * HIDDEN_DIM;
        float s = 0.f;
        for (int k = 0; k < HIDDEN_DIM; k++) s = fmaf(w[k], bo[k], s);
        bfinal[o] = s + bout[o];
    }
}

// ---------------------------------------------------------------------------
// SIMT tile GEMM body (128x128, 8x8/thread). Small split-K GEMMs.
// ---------------------------------------------------------------------------
template <bool BT>
__device__ __forceinline__ void sgemm_tile(int Klen, int lda, int ldb, int ldc,
                                           const float* __restrict__ A,
                                           const float* __restrict__ B,
                                           float* __restrict__ C, int bm, int bn) {
    __shared__ float As[8][128];
    __shared__ float Bs[8][128];
    const int tid = threadIdx.x;
    const int tx = tid & 15, ty = tid >> 4;
    float acc[8][8];
#pragma unroll
    for (int i = 0; i < 8; i++)
#pragma unroll
        for (int j = 0; j < 8; j++) acc[i][j] = 0.f;

    const int arow = tid >> 1, ak = (tid & 1) * 4;
    const int bkr = tid >> 5, bnc = (tid & 31) * 4;

    for (int k0 = 0; k0 < Klen; k0 += 8) {
        float4 av = *(const float4*)(A + (size_t)(bm + arow) * lda + k0 + ak);
        As[ak + 0][arow] = av.x; As[ak + 1][arow] = av.y;
        As[ak + 2][arow] = av.z; As[ak + 3][arow] = av.w;
        if (BT) {
            float4 bv = *(const float4*)(B + (size_t)(bn + arow) * ldb + k0 + ak);
            Bs[ak + 0][arow] = bv.x; Bs[ak + 1][arow] = bv.y;
            Bs[ak + 2][arow] = bv.z; Bs[ak + 3][arow] = bv.w;
        } else {
            float4 bv = *(const float4*)(B + (size_t)(k0 + bkr) * ldb + bn + bnc);
            *(float4*)&Bs[bkr][bnc] = bv;
        }
        __syncthreads();
#pragma unroll
        for (int kk = 0; kk < 8; kk++) {
            float a[8], b[8];
            *(float4*)&a[0] = *(const float4*)&As[kk][ty * 8];
            *(float4*)&a[4] = *(const float4*)&As[kk][ty * 8 + 4];
            *(float4*)&b[0] = *(const float4*)&Bs[kk][tx * 8];
            *(float4*)&b[4] = *(const float4*)&Bs[kk][tx * 8 + 4];
#pragma unroll
            for (int i = 0; i < 8; i++)
#pragma unroll
                for (int j = 0; j < 8; j++) acc[i][j] = fmaf(a[i], b[j], acc[i][j]);
        }
        __syncthreads();
    }
#pragma unroll
    for (int i = 0; i < 8; i++) {
        int row = bm + ty * 8 + i;
#pragma unroll
        for (int j = 0; j < 8; j += 4) {
            int col = bn + tx * 8 + j;
            *(float4*)(C + (size_t)row * ldc + col) = *(float4*)&acc[i][j];
        }
    }
}

// Weff partials: z -> (t = z/4, slice = z%4). Weff_t = W_in[t] @ W_t  (NN, K=512)
__global__ void __launch_bounds__(256)
weff_part_kernel(const float* __restrict__ W_in, const float* __restrict__ Wq,
                 const float* __restrict__ Wk, const float* __restrict__ Wv) {
    int t = blockIdx.z >> 2, sl = blockIdx.z & 3;
    const float* Bt = (t == 0) ? Wq : (t == 1 ? Wk : Wv);
    const float* A = W_in + (size_t)t * HIDDEN_DIM * HIDDEN_DIM + sl * 128;
    const float* B = Bt + (size_t)sl * 128 * INPUT_DIM;
    float* C = g_WeffPart + (size_t)sl * QKV_DIM * INPUT_DIM + (size_t)t * HIDDEN_DIM * INPUT_DIM;
    sgemm_tile<false>(128, HIDDEN_DIM, INPUT_DIM, INPUT_DIM, A, B, C,
                      blockIdx.y * 128, blockIdx.x * 128);
}

// Wfinal partials: Wfinal = Wout @ Wo (NN, K=512)
__global__ void __launch_bounds__(256)
wfinal_part_kernel(const float* __restrict__ Wout, const float* __restrict__ Wo) {
    int sl = blockIdx.z;
    sgemm_tile<false>(128, HIDDEN_DIM, HIDDEN_DIM, HIDDEN_DIM,
                      Wout + sl * 128, Wo + (size_t)sl * 128 * HIDDEN_DIM,
                      g_WfinalPart + (size_t)sl * OUTPUT_DIM * HIDDEN_DIM,
                      blockIdx.y * 128, blockIdx.x * 128);
}

// Final projection partials: out = pooled @ Wfinal^T (NT, K=512)
__global__ void __launch_bounds__(256)
out_part_kernel() {
    int sl = blockIdx.z;
    sgemm_tile<true>(128, HIDDEN_DIM, HIDDEN_DIM, OUTPUT_DIM,
                     g_pooled + sl * 128, g_Wfinal + sl * 128,
                     g_outPart + (size_t)sl * NUM_CELLS * OUTPUT_DIM,
                     blockIdx.y * 128, blockIdx.x * 128);
}

// ---------------------------------------------------------------------------
// Reductions
// ---------------------------------------------------------------------------
__device__ __forceinline__ void split_bf16(float x, __nv_bfloat16& h, __nv_bfloat16& l) {
    h = __float2bfloat16(x);
    l = __float2bfloat16(x - __bfloat162float(h));
}
__global__ void reduce_weff_kernel() {
    size_t i = (size_t)blockIdx.x * blockDim.x + threadIdx.x;
    const size_t n4 = (size_t)QKV_DIM * INPUT_DIM / 4;
    if (i >= n4) return;
    const size_t stride = (size_t)QKV_DIM * INPUT_DIM;
    float4 s = *(const float4*)(g_WeffPart + i * 4);
#pragma unroll
    for (int p = 1; p < SPLITK; p++) {
        float4 v = *(const float4*)(g_WeffPart + p * stride + i * 4);
        s.x += v.x; s.y += v.y; s.z += v.z; s.w += v.w;
    }
    __nv_bfloat16 h[4], l[4];
    split_bf16(s.x, h[0], l[0]); split_bf16(s.y, h[1], l[1]);
    split_bf16(s.z, h[2], l[2]); split_bf16(s.w, h[3], l[3]);
    *(uint2*)(g_Bhi + i * 4) = *(uint2*)h;
    *(uint2*)(g_Blo + i * 4) = *(uint2*)l;
}
__global__ void reduce_wfinal_kernel() {
    size_t i = (size_t)blockIdx.x * blockDim.x + threadIdx.x;
    const size_t n4 = (size_t)OUTPUT_DIM * HIDDEN_DIM / 4;
    if (i >= n4) return;
    const size_t stride = (size_t)OUTPUT_DIM * HIDDEN_DIM;
    float4 s = *(const float4*)(g_WfinalPart + i * 4);
#pragma unroll
    for (int p = 1; p < SPLITK; p++) {
        float4 v = *(const float4*)(g_WfinalPart + p * stride + i * 4);
        s.x += v.x; s.y += v.y; s.z += v.z; s.w += v.w;
    }
    *(float4*)(g_Wfinal + i * 4) = s;
}
__global__ void reduce_out_kernel(const float* __restrict__ bfinal, float* __restrict__ out) {
    size_t i = (size_t)blockIdx.x * blockDim.x + threadIdx.x;
    if (i >= (size_t)NUM_CELLS * OUTPUT_DIM) return;
    const size_t stride = (size_t)NUM_CELLS * OUTPUT_DIM;
    float s = bfinal[i & (OUTPUT_DIM - 1)];
#pragma unroll
    for (int p = 0; p < SPLITK; p++) s += g_outPart[p * stride + i];
    out[i] = s;
}

// ---------------------------------------------------------------------------
// chunk fp32 -> bf16 hi/lo (rows >= NUM_CHUNKS zero-padded to M_PAD)
// ---------------------------------------------------------------------------
__global__ void convert_chunk_kernel(const float* __restrict__ x) {
    size_t i = (size_t)blockIdx.x * blockDim.x + threadIdx.x;
    const size_t n4 = (size_t)M_PAD * INPUT_DIM / 4;
    if (i >= n4) return;
    float4 v = make_float4(0.f, 0.f, 0.f, 0.f);
    if (i * 4 < (size_t)NUM_CHUNKS * INPUT_DIM) v = *(const float4*)(x + i * 4);
    __nv_bfloat16 h[4], l[4];
    split_bf16(v.x, h[0], l[0]); split_bf16(v.y, h[1], l[1]);
    split_bf16(v.z, h[2], l[2]); split_bf16(v.w, h[3], l[3]);
    *(uint2*)(g_Ahi + i * 4) = *(uint2*)h;
    *(uint2*)(g_Alo + i * 4) = *(uint2*)l;
}

// ---------------------------------------------------------------------------
// QKV GEMM via mma.sync bf16: C[50048,1536] = A[*,768] @ B[1536,768]^T + beff
// 3-term split = 72 k-chunks of 32. CTA 128x128, warp 64x32, 3-stage cp.async.
// ---------------------------------------------------------------------------
__global__ void __launch_bounds__(256, 2)
qkv_mma_kernel(const float* __restrict__ beff, float* __restrict__ C) {
    extern __shared__ __align__(16) char smem[];
    const uint32_t sb = smem_u32(smem);
    const int tid = threadIdx.x, lane = tid & 31, wid = tid >> 5;
    const int bm = blockIdx.y * 128, bn = blockIdx.x * 128;
    const int wm = (wid & 1) * 64, wn = (wid >> 1) * 32;

    float c[4][4][4];
#pragma unroll
    for (int mt = 0; mt < 4; mt++)
#pragma unroll
        for (int nt = 0; nt < 4; nt++)
#pragma unroll
            for (int r = 0; r < 4; r++) c[mt][nt][r] = 0.f;

    // ldmatrix lane base offsets (A: [m][k] rows; B: [n][k] rows; row pitch 80B)
    const uint32_t a_off = (uint32_t)((wm + (lane & 15)) * ROWB + ((lane >> 4) & 1) * 16);
    const uint32_t b_off = (uint32_t)((wn + (lane & 7) + ((lane >> 4) & 1) * 8) * ROWB +
                                      ((lane >> 3) & 1) * 16);

    // cp.async mapping: two 16B units per operand per thread
    const int r0u = tid >> 2, s0u = tid & 3;          // unit tid
    const int r1u = (tid + 256) >> 2, s1u = tid & 3;  // unit tid+256

    auto issue = [&](int chunk) {
        int st = chunk % 3;
        int phase = chunk / 24, ko = (chunk % 24) * CHUNK_K;
        const __nv_bfloat16* As = (phase == 1) ? g_Alo : g_Ahi;
        const __nv_bfloat16* Bs = (phase == 2) ? g_Blo : g_Bhi;
        uint32_t sa = sb + st * STAGE_B;
        uint32_t sB = sa + TILE_BYTES;
        cp16(sa + r0u * ROWB + s0u * 16, As + (size_t)(bm + r0u) * INPUT_DIM + ko + s0u * 8);
        cp16(sB + r0u * ROWB + s0u * 16, Bs + (size_t)(bn + r0u) * INPUT_DIM + ko + s0u * 8);
        cp16(sa + r1u * ROWB + s1u * 16, As + (size_t)(bm + r1u) * INPUT_DIM + ko + s1u * 8);
        cp16(sB + r1u * ROWB + s1u * 16, Bs + (size_t)(bn + r1u) * INPUT_DIM + ko + s1u * 8);
        cp_commit();
    };

    issue(0);
    issue(1);

    for (int i = 0; i < NCHUNKS; i++) {
        if (i + 2 < NCHUNKS) issue(i + 2);
        cp_wait<2>();
        __syncthreads();
        uint32_t sa = sb + (i % 3) * STAGE_B;
        uint32_t sB = sa + TILE_BYTES;
#pragma unroll
        for (int ks = 0; ks < 2; ks++) {
            uint32_t kb = ks * 32;
            uint32_t a[4][4], b[2][4];
#pragma unroll
            for (int mt = 0; mt < 4; mt++)
                ldsm4(a[mt][0], a[mt][1], a[mt][2], a[mt][3],
                      sa + a_off + mt * 16 * ROWB + kb);
#pragma unroll
            for (int bt = 0; bt < 2; bt++)
                ldsm4(b[bt][0], b[bt][1], b[bt][2], b[bt][3],
                      sB + b_off + bt * 16 * ROWB + kb);
#pragma unroll
            for (int mt = 0; mt < 4; mt++)
#pragma unroll
                for (int nt = 0; nt < 4; nt++)
                    mma16816(c[mt][nt], a[mt][0], a[mt][1], a[mt][2], a[mt][3],
                             b[nt >> 1][(nt & 1) * 2], b[nt >> 1][(nt & 1) * 2 + 1]);
        }
        __syncthreads();
    }

    // epilogue: add bias, guarded stores (pad rows skipped)
    const int rr = bm + wm + (lane >> 2);
    const int cc = bn + wn + (lane & 3) * 2;
#pragma unroll
    for (int mt = 0; mt < 4; mt++) {
#pragma unroll
        for (int nt = 0; nt < 4; nt++) {
            int col = cc + nt * 8;
            float b0 = beff[col], b1 = beff[col + 1];
            int row = rr + mt * 16;
            if (row < NUM_CHUNKS) {
                float2 v = make_float2(c[mt][nt][0] + b0, c[mt][nt][1] + b1);
                *(float2*)(C + (size_t)row * QKV_DIM + col) = v;
            }
            if (row + 8 < NUM_CHUNKS) {
                float2 v = make_float2(c[mt][nt][2] + b0, c[mt][nt][3] + b1);
                *(float2*)(C + (size_t)(row + 8) * QKV_DIM + col) = v;
            }
        }
    }
}

// ---------------------------------------------------------------------------
// Attention + masked mean pool (validated in R3)
// ---------------------------------------------------------------------------
__global__ void __launch_bounds__(256)
attn_pool_kernel(const float* __restrict__ QKV, const void* __restrict__ cell_idx,
                 const void* __restrict__ cell_len, float* __restrict__ pooled) {
    __shared__ float qs[64][66];
    __shared__ float ks[64][66];
    __shared__ float wsum[64];
    __shared__ float part[4][64];
    __shared__ int ridx[64];

    const int c = blockIdx.x, h = blockIdx.y, tid = threadIdx.x;
    const int hoff = h * HEAD_DIM;
    const int sI = g_idx_is64 ? 2 : 1;
    const int sL = g_len_is64 ? 2 : 1;
    const int* idx32 = (const int*)cell_idx;
    const int* len32 = (const int*)cell_len;

    int len = len32[(size_t)c * sL];
    int Leff = len < 1 ? 1 : (len > 64 ? 64 : len);
    if (tid < 64) ridx[tid] = idx32[((size_t)c * MAX_LEN + tid) * sI];
    __syncthreads();

    for (int e = tid; e < 64 * 16; e += 256) {
        int l = e >> 4, d4 = (e & 15) << 2;
        float4 qv = make_float4(0.f, 0.f, 0.f, 0.f);
        float4 kv = make_float4(0.f, 0.f, 0.f, 0.f);
        if (l < Leff) {
            size_t base = (size_t)ridx[l] * QKV_DIM + hoff + d4;
            qv = *(const float4*)(QKV + base);
            kv = *(const float4*)(QKV + base + HIDDEN_DIM);
        }
        qs[l][d4 + 0] = qv.x; qs[l][d4 + 1] = qv.y; qs[l][d4 + 2] = qv.z; qs[l][d4 + 3] = qv.w;
        ks[l][d4 + 0] = kv.x; ks[l][d4 + 1] = kv.y; ks[l][d4 + 2] = kv.z; ks[l][d4 + 3] = kv.w;
    }
    __syncthreads();

    const int l = tid >> 2, g = tid & 3;
    float p[16];
    float rmax = -1e30f;
#pragma unroll
    for (int j = 0; j < 16; j++) {
        int m = g * 16 + j;
        float acc = 0.f;
#pragma unroll
        for (int d = 0; d < 64; d++) acc = fmaf(qs[l][d], ks[m][d], acc);
        float s = (m < Leff) ? acc * 0.125f : -1e30f;
        p[j] = s;
        rmax = fmaxf(rmax, s);
    }
    rmax = fmaxf(rmax, __shfl_xor_sync(0xffffffffu, rmax, 1));
    rmax = fmaxf(rmax, __shfl_xor_sync(0xffffffffu, rmax, 2));
    float rsum = 0.f;
#pragma unroll
    for (int j = 0; j < 16; j++) {
        int m = g * 16 + j;
        float e = (m < Leff) ? __expf(p[j] - rmax) : 0.f;
        p[j] = e;
        rsum += e;
    }
    rsum += __shfl_xor_sync(0xffffffffu, rsum, 1);
    rsum += __shfl_xor_sync(0xffffffffu, rsum, 2);
    float inv = 1.f / rsum;
    __syncthreads();
    if (l < Leff) {
#pragma unroll
        for (int j = 0; j < 16; j++) qs[l][g * 16 + j] = p[j] * inv;
    }
    __syncthreads();
    if (tid < 64) {
        float s = 0.f;
        for (int ll = 0; ll < Leff; ll++) s += qs[ll][tid];
        wsum[tid] = s / (float)Leff;
    }
    __syncthreads();
    const int pt = tid >> 6, d = tid & 63;
    float acc = 0.f;
    for (int m = pt; m < Leff; m += 4)
        acc = fmaf(wsum[m], QKV[(size_t)ridx[m] * QKV_DIM + 2 * HIDDEN_DIM + hoff + d], acc);
    part[pt][d] = acc;
    __syncthreads();
    if (tid < 64)
        pooled[(size_t)c * HIDDEN_DIM + hoff + tid] =
            part[0][tid] + part[1][tid] + part[2][tid] + part[3][tid];
}

// ---------------------------------------------------------------------------
// Launch
// ---------------------------------------------------------------------------
extern "C" void kernel_launch(void* const* d_in, const int* in_sizes, int n_in,
                              void* d_out, int out_size) {
    const float* chunk = (const float*)d_in[0];
    const float* Wq   = (const float*)d_in[1];
    const float* bq   = (const float*)d_in[2];
    const float* Wk   = (const float*)d_in[3];
    const float* bk   = (const float*)d_in[4];
    const float* Wv   = (const float*)d_in[5];
    const float* bv   = (const float*)d_in[6];
    const float* W_in = (const float*)d_in[7];
    const float* b_in = (const float*)d_in[8];
    const float* Wo   = (const float*)d_in[9];
    const float* bo   = (const float*)d_in[10];
    const float* Wout = (const float*)d_in[11];
    const float* bout = (const float*)d_in[12];
    const void*  cidx = d_in[13];
    const void*  clen = d_in[14];
    float* out = (float*)d_out;

    float *pQKV, *pbeff, *pPooled, *pbfinal;
    cudaGetSymbolAddress((void**)&pQKV, g_QKV);
    cudaGetSymbolAddress((void**)&pbeff, g_beff);
    cudaGetSymbolAddress((void**)&pPooled, g_pooled);
    cudaGetSymbolAddress((void**)&pbfinal, g_bfinal);

    static bool attr_set = false;
    if (!attr_set) {
        cudaFuncSetAttribute(qkv_mma_kernel, cudaFuncAttributeMaxDynamicSharedMemorySize,
                             SMEM_MMA);
        attr_set = true;
    }

    // 0) dtype detection
    detect_dtype_kernel<<<1, 32>>>((const int*)cidx, (const int*)clen);

    // 1) combined biases
    combine_bias_kernel<<<(QKV_DIM + OUTPUT_DIM + 255) / 256, 256>>>(
        W_in, b_in, bq, bk, bv, Wout, bo, bout, pbeff, pbfinal);

    // 2) small GEMMs via split-K partials + deterministic reduce
    weff_part_kernel<<<dim3(INPUT_DIM / 128, HIDDEN_DIM / 128, 3 * SPLITK), 256>>>(
        W_in, Wq, Wk, Wv);
    wfinal_part_kernel<<<dim3(HIDDEN_DIM / 128, OUTPUT_DIM / 128, SPLITK), 256>>>(Wout, Wo);
    reduce_weff_kernel<<<(QKV_DIM * INPUT_DIM / 4 + 255) / 256, 256>>>();
    reduce_wfinal_kernel<<<(OUTPUT_DIM * HIDDEN_DIM / 4 + 255) / 256, 256>>>();

    // 3) chunk -> bf16 hi/lo
    convert_chunk_kernel<<<((size_t)M_PAD * INPUT_DIM / 4 + 255) / 256, 256>>>(chunk);

    // 4) QKV projection on tensor cores (mma.sync)
    qkv_mma_kernel<<<dim3(QKV_DIM / 128, M_PAD / 128), 256, SMEM_MMA>>>(pbeff, pQKV);

    // 5) fused attention + masked mean pool
    attn_pool_kernel<<<dim3(NUM_CELLS, NUM_HEADS), 256>>>(pQKV, cidx, clen, pPooled);

    // 6) final projection (split-K partials + reduce with bias)
    out_part_kernel<<<dim3(OUTPUT_DIM / 128, NUM_CELLS / 128, SPLITK), 256>>>();
    reduce_out_kernel<<<(NUM_CELLS * OUTPUT_DIM + 255) / 256, 256>>>(pbfinal, out);
}

// round 6
// speedup vs baseline: 3.3201x; 3.2843x over previous
#include <cuda_runtime.h>
#include <cuda_bf16.h>
#include <math.h>
#include <stdint.h>

// ---------------------------------------------------------------------------
// Problem constants
// ---------------------------------------------------------------------------
#define NUM_HEADS   8
#define NUM_CHUNKS  50000
#define INPUT_DIM   768
#define HIDDEN_DIM  512
#define OUTPUT_DIM  256
#define NUM_CELLS   2048
#define MAX_LEN     64
#define HEAD_DIM    64
#define QKV_DIM     1536
#define M_PAD       50048              // 391 * 128
#define SPLITK      4

// mma GEMM geometry (k-chunk 64, swizzled smem, 3 stages)
#define CHUNK_K     64
#define NCHUNKS     36                 // 3 split phases * (768/64)
#define TILE_BYTES  (128 * 128)        // 16384 (128 rows x 128B swizzled)
#define STAGE_B     (2 * TILE_BYTES)   // 32768
#define SMEM_MMA    (3 * STAGE_B)      // 98304

// ---------------------------------------------------------------------------
// Device-global scratch (allocation-free contract)
// ---------------------------------------------------------------------------
__device__ __align__(1024) __nv_bfloat16 g_Ahi[(size_t)M_PAD * INPUT_DIM];
__device__ __align__(1024) __nv_bfloat16 g_Alo[(size_t)M_PAD * INPUT_DIM];
__device__ __align__(1024) __nv_bfloat16 g_Bhi[QKV_DIM * INPUT_DIM];
__device__ __align__(1024) __nv_bfloat16 g_Blo[QKV_DIM * INPUT_DIM];
__device__ __align__(256) float g_QKV[(size_t)NUM_CHUNKS * QKV_DIM];
__device__ __align__(256) float g_beff[QKV_DIM];
__device__ __align__(256) float g_pooled[NUM_CELLS * HIDDEN_DIM];
__device__ __align__(256) float g_Wfinal[OUTPUT_DIM * HIDDEN_DIM];
__device__ __align__(256) float g_bfinal[OUTPUT_DIM];
__device__ __align__(256) float g_WeffPart[SPLITK * QKV_DIM * INPUT_DIM];
__device__ __align__(256) float g_WfinalPart[SPLITK * OUTPUT_DIM * HIDDEN_DIM];
__device__ __align__(256) float g_outPart[SPLITK * NUM_CELLS * OUTPUT_DIM];
__device__ int g_idx_is64;
__device__ int g_len_is64;

// ---------------------------------------------------------------------------
// PTX helpers (plain-sm_80-level: safe for non-'a' ptx target)
// ---------------------------------------------------------------------------
__device__ __forceinline__ uint32_t smem_u32(const void* p) {
    uint32_t a;
    asm("{ .reg .u64 t; cvta.to.shared.u64 t, %1; cvt.u32.u64 %0, t; }"
        : "=r"(a) : "l"(p));
    return a;
}
__device__ __forceinline__ void cp16(uint32_t d, const void* s) {
    asm volatile("cp.async.cg.shared.global [%0], [%1], 16;" :: "r"(d), "l"(s));
}
__device__ __forceinline__ void cp_commit() {
    asm volatile("cp.async.commit_group;" ::: "memory");
}
template <int N>
__device__ __forceinline__ void cp_wait() {
    asm volatile("cp.async.wait_group %0;" :: "n"(N) : "memory");
}
__device__ __forceinline__ void ldsm4(uint32_t& r0, uint32_t& r1, uint32_t& r2,
                                      uint32_t& r3, uint32_t a) {
    asm volatile("ldmatrix.sync.aligned.m8n8.x4.shared.b16 {%0,%1,%2,%3}, [%4];"
                 : "=r"(r0), "=r"(r1), "=r"(r2), "=r"(r3) : "r"(a));
}
__device__ __forceinline__ void mma16816(float* c, uint32_t a0, uint32_t a1,
                                         uint32_t a2, uint32_t a3,
                                         uint32_t b0, uint32_t b1) {
    asm volatile("mma.sync.aligned.m16n8k16.row.col.f32.bf16.bf16.f32 "
                 "{%0,%1,%2,%3}, {%4,%5,%6,%7}, {%8,%9}, {%0,%1,%2,%3};"
                 : "+f"(c[0]), "+f"(c[1]), "+f"(c[2]), "+f"(c[3])
                 : "r"(a0), "r"(a1), "r"(a2), "r"(a3), "r"(b0), "r"(b1));
}

// ---------------------------------------------------------------------------
// dtype detection (int64 vs silently-downcast int32 indices)
// ---------------------------------------------------------------------------
__global__ void detect_dtype_kernel(const int* __restrict__ iw, const int* __restrict__ lw) {
    if (threadIdx.x == 0 && blockIdx.x == 0) {
        int oi = 0, ol = 0;
        for (int i = 0; i < 256; i++) oi |= iw[2 * i + 1];
        for (int i = 0; i < 256; i++) ol |= lw[2 * i + 1];
        g_idx_is64 = (oi == 0) ? 1 : 0;
        g_len_is64 = (ol == 0) ? 1 : 0;
    }
}

// ---------------------------------------------------------------------------
// Combined biases
// ---------------------------------------------------------------------------
__global__ void combine_bias_kernel(const float* __restrict__ W_in, const float* __restrict__ b_in,
                                    const float* __restrict__ bq, const float* __restrict__ bk,
                                    const float* __restrict__ bv, const float* __restrict__ Wout,
                                    const float* __restrict__ bo, const float* __restrict__ bout,
                                    float* __restrict__ beff, float* __restrict__ bfinal) {
    int i = blockIdx.x * blockDim.x + threadIdx.x;
    if (i < QKV_DIM) {
        const float* bs = (i < HIDDEN_DIM) ? bq : (i < 2 * HIDDEN_DIM ? bk : bv);
        const float* w = W_in + (size_t)i * HIDDEN_DIM;
        float s = 0.f;
        for (int k = 0; k < HIDDEN_DIM; k++) s = fmaf(w[k], bs[k], s);
        beff[i] = s + b_in[i];
    } else if (i < QKV_DIM + OUTPUT_DIM) {
        int o = i - QKV_DIM;
        const float* w = Wout + (size_t)o * HIDDEN_DIM;
        float s = 0.f;
        for (int k = 0; k < HIDDEN_DIM; k++) s = fmaf(w[k], bo[k], s);
        bfinal[o] = s + bout[o];
    }
}

// ---------------------------------------------------------------------------
// SIMT tile GEMM body (128x128, 8x8/thread). Small split-K GEMMs.
// ---------------------------------------------------------------------------
template <bool BT>
__device__ __forceinline__ void sgemm_tile(int Klen, int lda, int ldb, int ldc,
                                           const float* __restrict__ A,
                                           const float* __restrict__ B,
                                           float* __restrict__ C, int bm, int bn) {
    __shared__ float As[8][128];
    __shared__ float Bs[8][128];
    const int tid = threadIdx.x;
    const int tx = tid & 15, ty = tid >> 4;
    float acc[8][8];
#pragma unroll
    for (int i = 0; i < 8; i++)
#pragma unroll
        for (int j = 0; j < 8; j++) acc[i][j] = 0.f;

    const int arow = tid >> 1, ak = (tid & 1) * 4;
    const int bkr = tid >> 5, bnc = (tid & 31) * 4;

    for (int k0 = 0; k0 < Klen; k0 += 8) {
        float4 av = *(const float4*)(A + (size_t)(bm + arow) * lda + k0 + ak);
        As[ak + 0][arow] = av.x; As[ak + 1][arow] = av.y;
        As[ak + 2][arow] = av.z; As[ak + 3][arow] = av.w;
        if (BT) {
            float4 bv = *(const float4*)(B + (size_t)(bn + arow) * ldb + k0 + ak);
            Bs[ak + 0][arow] = bv.x; Bs[ak + 1][arow] = bv.y;
            Bs[ak + 2][arow] = bv.z; Bs[ak + 3][arow] = bv.w;
        } else {
            float4 bv = *(const float4*)(B + (size_t)(k0 + bkr) * ldb + bn + bnc);
            *(float4*)&Bs[bkr][bnc] = bv;
        }
        __syncthreads();
#pragma unroll
        for (int kk = 0; kk < 8; kk++) {
            float a[8], b[8];
            *(float4*)&a[0] = *(const float4*)&As[kk][ty * 8];
            *(float4*)&a[4] = *(const float4*)&As[kk][ty * 8 + 4];
            *(float4*)&b[0] = *(const float4*)&Bs[kk][tx * 8];
            *(float4*)&b[4] = *(const float4*)&Bs[kk][tx * 8 + 4];
#pragma unroll
            for (int i = 0; i < 8; i++)
#pragma unroll
                for (int j = 0; j < 8; j++) acc[i][j] = fmaf(a[i], b[j], acc[i][j]);
        }
        __syncthreads();
    }
#pragma unroll
    for (int i = 0; i < 8; i++) {
        int row = bm + ty * 8 + i;
#pragma unroll
        for (int j = 0; j < 8; j += 4) {
            int col = bn + tx * 8 + j;
            *(float4*)(C + (size_t)row * ldc + col) = *(float4*)&acc[i][j];
        }
    }
}

__global__ void __launch_bounds__(256)
weff_part_kernel(const float* __restrict__ W_in, const float* __restrict__ Wq,
                 const float* __restrict__ Wk, const float* __restrict__ Wv) {
    int t = blockIdx.z >> 2, sl = blockIdx.z & 3;
    const float* Bt = (t == 0) ? Wq : (t == 1 ? Wk : Wv);
    const float* A = W_in + (size_t)t * HIDDEN_DIM * HIDDEN_DIM + sl * 128;
    const float* B = Bt + (size_t)sl * 128 * INPUT_DIM;
    float* C = g_WeffPart + (size_t)sl * QKV_DIM * INPUT_DIM + (size_t)t * HIDDEN_DIM * INPUT_DIM;
    sgemm_tile<false>(128, HIDDEN_DIM, INPUT_DIM, INPUT_DIM, A, B, C,
                      blockIdx.y * 128, blockIdx.x * 128);
}

__global__ void __launch_bounds__(256)
wfinal_part_kernel(const float* __restrict__ Wout, const float* __restrict__ Wo) {
    int sl = blockIdx.z;
    sgemm_tile<false>(128, HIDDEN_DIM, HIDDEN_DIM, HIDDEN_DIM,
                      Wout + sl * 128, Wo + (size_t)sl * 128 * HIDDEN_DIM,
                      g_WfinalPart + (size_t)sl * OUTPUT_DIM * HIDDEN_DIM,
                      blockIdx.y * 128, blockIdx.x * 128);
}

__global__ void __launch_bounds__(256)
out_part_kernel() {
    int sl = blockIdx.z;
    sgemm_tile<true>(128, HIDDEN_DIM, HIDDEN_DIM, OUTPUT_DIM,
                     g_pooled + sl * 128, g_Wfinal + sl * 128,
                     g_outPart + (size_t)sl * NUM_CELLS * OUTPUT_DIM,
                     blockIdx.y * 128, blockIdx.x * 128);
}

// ---------------------------------------------------------------------------
// Reductions
// ---------------------------------------------------------------------------
__device__ __forceinline__ void split_bf16(float x, __nv_bfloat16& h, __nv_bfloat16& l) {
    h = __float2bfloat16(x);
    l = __float2bfloat16(x - __bfloat162float(h));
}
__global__ void reduce_weff_kernel() {
    size_t i = (size_t)blockIdx.x * blockDim.x + threadIdx.x;
    const size_t n4 = (size_t)QKV_DIM * INPUT_DIM / 4;
    if (i >= n4) return;
    const size_t stride = (size_t)QKV_DIM * INPUT_DIM;
    float4 s = *(const float4*)(g_WeffPart + i * 4);
#pragma unroll
    for (int p = 1; p < SPLITK; p++) {
        float4 v = *(const float4*)(g_WeffPart + p * stride + i * 4);
        s.x += v.x; s.y += v.y; s.z += v.z; s.w += v.w;
    }
    __nv_bfloat16 h[4], l[4];
    split_bf16(s.x, h[0], l[0]); split_bf16(s.y, h[1], l[1]);
    split_bf16(s.z, h[2], l[2]); split_bf16(s.w, h[3], l[3]);
    *(uint2*)(g_Bhi + i * 4) = *(uint2*)h;
    *(uint2*)(g_Blo + i * 4) = *(uint2*)l;
}
__global__ void reduce_wfinal_kernel() {
    size_t i = (size_t)blockIdx.x * blockDim.x + threadIdx.x;
    const size_t n4 = (size_t)OUTPUT_DIM * HIDDEN_DIM / 4;
    if (i >= n4) return;
    const size_t stride = (size_t)OUTPUT_DIM * HIDDEN_DIM;
    float4 s = *(const float4*)(g_WfinalPart + i * 4);
#pragma unroll
    for (int p = 1; p < SPLITK; p++) {
        float4 v = *(const float4*)(g_WfinalPart + p * stride + i * 4);
        s.x += v.x; s.y += v.y; s.z += v.z; s.w += v.w;
    }
    *(float4*)(g_Wfinal + i * 4) = s;
}
__global__ void reduce_out_kernel(const float* __restrict__ bfinal, float* __restrict__ out) {
    size_t i = (size_t)blockIdx.x * blockDim.x + threadIdx.x;
    if (i >= (size_t)NUM_CELLS * OUTPUT_DIM) return;
    const size_t stride = (size_t)NUM_CELLS * OUTPUT_DIM;
    float s = bfinal[i & (OUTPUT_DIM - 1)];
#pragma unroll
    for (int p = 0; p < SPLITK; p++) s += g_outPart[p * stride + i];
    out[i] = s;
}

// ---------------------------------------------------------------------------
// chunk fp32 -> bf16 hi/lo (rows >= NUM_CHUNKS zero-padded to M_PAD)
// ---------------------------------------------------------------------------
__global__ void convert_chunk_kernel(const float* __restrict__ x) {
    size_t i = (size_t)blockIdx.x * blockDim.x + threadIdx.x;
    const size_t n4 = (size_t)M_PAD * INPUT_DIM / 4;
    if (i >= n4) return;
    float4 v = make_float4(0.f, 0.f, 0.f, 0.f);
    if (i * 4 < (size_t)NUM_CHUNKS * INPUT_DIM) v = *(const float4*)(x + i * 4);
    __nv_bfloat16 h[4], l[4];
    split_bf16(v.x, h[0], l[0]); split_bf16(v.y, h[1], l[1]);
    split_bf16(v.z, h[2], l[2]); split_bf16(v.w, h[3], l[3]);
    *(uint2*)(g_Ahi + i * 4) = *(uint2*)h;
    *(uint2*)(g_Alo + i * 4) = *(uint2*)l;
}

// ---------------------------------------------------------------------------
// QKV GEMM via mma.sync bf16, swizzled smem, k-chunk 64, 3 stages, 1 sync/iter.
// C[50048,1536] = A[*,768] @ B[1536,768]^T + beff  (3-term bf16 split)
// Swizzle: byte = row*128 + (col16B*16 ^ ((row&7)<<4)); row&7 == lane&7 for all
// fragments, so the XOR is a per-lane constant.
// ---------------------------------------------------------------------------
__global__ void __launch_bounds__(256, 2)
qkv_mma_kernel(const float* __restrict__ beff, float* __restrict__ C) {
    extern __shared__ __align__(128) char smem[];
    const uint32_t sb = smem_u32(smem);
    const int tid = threadIdx.x, lane = tid & 31, wid = tid >> 5;
    const int bm = blockIdx.y * 128, bn = blockIdx.x * 128;
    const int wm = (wid & 1) * 64, wn = (wid >> 1) * 32;

    float c[4][4][4];
#pragma unroll
    for (int mt = 0; mt < 4; mt++)
#pragma unroll
        for (int nt = 0; nt < 4; nt++)
#pragma unroll
            for (int r = 0; r < 4; r++) c[mt][nt][r] = 0.f;

    // per-lane ldmatrix bases
    const uint32_t sw   = (uint32_t)((lane & 7) << 4);
    const int arow = wm + (lane & 15);
    const uint32_t ahi  = (uint32_t)(((lane >> 4) & 1) * 16);
    const int brow = wn + (lane & 7) + ((lane >> 4) & 1) * 8;
    const uint32_t bhi  = (uint32_t)(((lane >> 3) & 1) * 16);

    // cp.async: 8 x 16B units per thread (A tile 1024 units, B tile 1024)
    auto issue = [&](int chunk) {
        int st = chunk % 3;
        int phase = chunk / 12, ko = (chunk % 12) * CHUNK_K;
        const __nv_bfloat16* As = (phase == 1) ? g_Alo : g_Ahi;
        const __nv_bfloat16* Bs = (phase == 2) ? g_Blo : g_Bhi;
        uint32_t base = sb + st * STAGE_B;
#pragma unroll
        for (int i = 0; i < 8; i++) {
            int u = tid + 256 * i;
            int row = (u >> 3) & 127;
            int c16 = u & 7;
            bool isB = u >= 1024;
            uint32_t dst = base + (isB ? TILE_BYTES : 0) + row * 128 +
                           ((uint32_t)(c16 * 16) ^ (uint32_t)((row & 7) << 4));
            const __nv_bfloat16* src =
                isB ? Bs + (size_t)(bn + row) * INPUT_DIM + ko + c16 * 8
                    : As + (size_t)(bm + row) * INPUT_DIM + ko + c16 * 8;
            cp16(dst, src);
        }
        cp_commit();
    };

    issue(0);
    issue(1);

    for (int i = 0; i < NCHUNKS; i++) {
        cp_wait<1>();
        __syncthreads();   // all warps done with stage (i-1)%3; stage i%3 visible
        if (i + 2 < NCHUNKS) issue(i + 2);   // refills stage (i-1)%3
        else cp_commit();                    // keep group count aligned
        uint32_t sa = sb + (i % 3) * STAGE_B;
        uint32_t sB = sa + TILE_BYTES;
#pragma unroll
        for (int kf = 0; kf < 4; kf++) {
            uint32_t a[4][4], b[2][4];
#pragma unroll
            for (int mt = 0; mt < 4; mt++)
                ldsm4(a[mt][0], a[mt][1], a[mt][2], a[mt][3],
                      sa + (uint32_t)(arow + mt * 16) * 128 +
                          (((uint32_t)(kf * 32) + ahi) ^ sw));
#pragma unroll
            for (int bt = 0; bt < 2; bt++)
                ldsm4(b[bt][0], b[bt][1], b[bt][2], b[bt][3],
                      sB + (uint32_t)(brow + bt * 16) * 128 +
                          (((uint32_t)(kf * 32) + bhi) ^ sw));
#pragma unroll
            for (int mt = 0; mt < 4; mt++)
#pragma unroll
                for (int nt = 0; nt < 4; nt++)
                    mma16816(c[mt][nt], a[mt][0], a[mt][1], a[mt][2], a[mt][3],
                             b[nt >> 1][(nt & 1) * 2], b[nt >> 1][(nt & 1) * 2 + 1]);
        }
    }

    // epilogue: add bias, guarded stores (pad rows skipped)
    const int rr = bm + wm + (lane >> 2);
    const int cc = bn + wn + (lane & 3) * 2;
#pragma unroll
    for (int mt = 0; mt < 4; mt++) {
#pragma unroll
        for (int nt = 0; nt < 4; nt++) {
            int col = cc + nt * 8;
            float b0 = beff[col], b1 = beff[col + 1];
            int row = rr + mt * 16;
            if (row < NUM_CHUNKS) {
                float2 v = make_float2(c[mt][nt][0] + b0, c[mt][nt][1] + b1);
                *(float2*)(C + (size_t)row * QKV_DIM + col) = v;
            }
            if (row + 8 < NUM_CHUNKS) {
                float2 v = make_float2(c[mt][nt][2] + b0, c[mt][nt][3] + b1);
                *(float2*)(C + (size_t)(row + 8) * QKV_DIM + col) = v;
            }
        }
    }
}

// ---------------------------------------------------------------------------
// Attention + masked mean pool. Bank-conflict-free layout:
//   row stride 68 floats; thread (l = tid>>2, g = tid&3) owns keys m = g + 4j.
//   ks LDS: banks (68m+d)%32 = (4g+16j+d)%32 -> 4 distinct banks per access.
// q register-blocked (16 floats) to halve LDS instruction count.
// ---------------------------------------------------------------------------
__global__ void __launch_bounds__(256)
attn_pool_kernel(const float* __restrict__ QKV, const void* __restrict__ cell_idx,
                 const void* __restrict__ cell_len, float* __restrict__ pooled) {
    __shared__ float qs[64][68];
    __shared__ float ks[64][68];
    __shared__ float wsum[64];
    __shared__ float part[4][64];
    __shared__ int ridx[64];

    const int c = blockIdx.x, h = blockIdx.y, tid = threadIdx.x;
    const int hoff = h * HEAD_DIM;
    const int sI = g_idx_is64 ? 2 : 1;
    const int sL = g_len_is64 ? 2 : 1;
    const int* idx32 = (const int*)cell_idx;
    const int* len32 = (const int*)cell_len;

    int len = len32[(size_t)c * sL];
    int Leff = len < 1 ? 1 : (len > 64 ? 64 : len);
    if (tid < 64) ridx[tid] = idx32[((size_t)c * MAX_LEN + tid) * sI];
    __syncthreads();

    for (int e = tid; e < 64 * 16; e += 256) {
        int l = e >> 4, d4 = (e & 15) << 2;
        float4 qv = make_float4(0.f, 0.f, 0.f, 0.f);
        float4 kv = make_float4(0.f, 0.f, 0.f, 0.f);
        if (l < Leff) {
            size_t base = (size_t)ridx[l] * QKV_DIM + hoff + d4;
            qv = *(const float4*)(QKV + base);
            kv = *(const float4*)(QKV + base + HIDDEN_DIM);
        }
        qs[l][d4 + 0] = qv.x; qs[l][d4 + 1] = qv.y; qs[l][d4 + 2] = qv.z; qs[l][d4 + 3] = qv.w;
        ks[l][d4 + 0] = kv.x; ks[l][d4 + 1] = kv.y; ks[l][d4 + 2] = kv.z; ks[l][d4 + 3] = kv.w;
    }
    __syncthreads();

    const int l = tid >> 2, g = tid & 3;
    float p[16];
#pragma unroll
    for (int j = 0; j < 16; j++) p[j] = 0.f;
#pragma unroll
    for (int db = 0; db < 64; db += 16) {
        float qr[16];
#pragma unroll
        for (int t = 0; t < 16; t++) qr[t] = qs[l][db + t];
#pragma unroll
        for (int j = 0; j < 16; j++) {
            const int m = g + 4 * j;
            float s = p[j];
#pragma unroll
            for (int t = 0; t < 16; t++) s = fmaf(qr[t], ks[m][db + t], s);
            p[j] = s;
        }
    }

    float rmax = -1e30f;
#pragma unroll
    for (int j = 0; j < 16; j++) {
        int m = g + 4 * j;
        float s = (m < Leff) ? p[j] * 0.125f : -1e30f;  // 1/sqrt(64)
        p[j] = s;
        rmax = fmaxf(rmax, s);
    }
    rmax = fmaxf(rmax, __shfl_xor_sync(0xffffffffu, rmax, 1));
    rmax = fmaxf(rmax, __shfl_xor_sync(0xffffffffu, rmax, 2));
    float rsum = 0.f;
#pragma unroll
    for (int j = 0; j < 16; j++) {
        int m = g + 4 * j;
        float e = (m < Leff) ? __expf(p[j] - rmax) : 0.f;
        p[j] = e;
        rsum += e;
    }
    rsum += __shfl_xor_sync(0xffffffffu, rsum, 1);
    rsum += __shfl_xor_sync(0xffffffffu, rsum, 2);
    float inv = 1.f / rsum;
    __syncthreads();   // done reading qs -> safe to overwrite with probs
    if (l < Leff) {
#pragma unroll
        for (int j = 0; j < 16; j++) qs[l][g + 4 * j] = p[j] * inv;
    }
    __syncthreads();
    if (tid < 64) {
        float s = 0.f;
        for (int ll = 0; ll < Leff; ll++) s += qs[ll][tid];
        wsum[tid] = s / (float)Leff;
    }
    __syncthreads();
    const int pt = tid >> 6, d = tid & 63;
    float acc = 0.f;
    for (int m = pt; m < Leff; m += 4)
        acc = fmaf(wsum[m], QKV[(size_t)ridx[m] * QKV_DIM + 2 * HIDDEN_DIM + hoff + d], acc);
    part[pt][d] = acc;
    __syncthreads();
    if (tid < 64)
        pooled[(size_t)c * HIDDEN_DIM + hoff + tid] =
            part[0][tid] + part[1][tid] + part[2][tid] + part[3][tid];
}

// ---------------------------------------------------------------------------
// Launch
// ---------------------------------------------------------------------------
extern "C" void kernel_launch(void* const* d_in, const int* in_sizes, int n_in,
                              void* d_out, int out_size) {
    const float* chunk = (const float*)d_in[0];
    const float* Wq   = (const float*)d_in[1];
    const float* bq   = (const float*)d_in[2];
    const float* Wk   = (const float*)d_in[3];
    const float* bk   = (const float*)d_in[4];
    const float* Wv   = (const float*)d_in[5];
    const float* bv   = (const float*)d_in[6];
    const float* W_in = (const float*)d_in[7];
    const float* b_in = (const float*)d_in[8];
    const float* Wo   = (const float*)d_in[9];
    const float* bo   = (const float*)d_in[10];
    const float* Wout = (const float*)d_in[11];
    const float* bout = (const float*)d_in[12];
    const void*  cidx = d_in[13];
    const void*  clen = d_in[14];
    float* out = (float*)d_out;

    float *pQKV, *pbeff, *pPooled, *pbfinal;
    cudaGetSymbolAddress((void**)&pQKV, g_QKV);
    cudaGetSymbolAddress((void**)&pbeff, g_beff);
    cudaGetSymbolAddress((void**)&pPooled, g_pooled);
    cudaGetSymbolAddress((void**)&pbfinal, g_bfinal);

    static bool attr_set = false;
    if (!attr_set) {
        cudaFuncSetAttribute(qkv_mma_kernel, cudaFuncAttributeMaxDynamicSharedMemorySize,
                             SMEM_MMA);
        attr_set = true;
    }

    // 0) dtype detection
    detect_dtype_kernel<<<1, 32>>>((const int*)cidx, (const int*)clen);

    // 1) combined biases
    combine_bias_kernel<<<(QKV_DIM + OUTPUT_DIM + 255) / 256, 256>>>(
        W_in, b_in, bq, bk, bv, Wout, bo, bout, pbeff, pbfinal);

    // 2) small GEMMs via split-K partials + deterministic reduce
    weff_part_kernel<<<dim3(INPUT_DIM / 128, HIDDEN_DIM / 128, 3 * SPLITK), 256>>>(
        W_in, Wq, Wk, Wv);
    wfinal_part_kernel<<<dim3(HIDDEN_DIM / 128, OUTPUT_DIM / 128, SPLITK), 256>>>(Wout, Wo);
    reduce_weff_kernel<<<(QKV_DIM * INPUT_DIM / 4 + 255) / 256, 256>>>();
    reduce_wfinal_kernel<<<(OUTPUT_DIM * HIDDEN_DIM / 4 + 255) / 256, 256>>>();

    // 3) chunk -> bf16 hi/lo
    convert_chunk_kernel<<<((size_t)M_PAD * INPUT_DIM / 4 + 255) / 256, 256>>>(chunk);

    // 4) QKV projection on tensor cores (mma.sync, swizzled pipeline)
    qkv_mma_kernel<<<dim3(QKV_DIM / 128, M_PAD / 128), 256, SMEM_MMA>>>(pbeff, pQKV);

    // 5) fused attention + masked mean pool (conflict-free layout)
    attn_pool_kernel<<<dim3(NUM_CELLS, NUM_HEADS), 256>>>(pQKV, cidx, clen, pPooled);

    // 6) final projection (split-K partials + reduce with bias)
    out_part_kernel<<<dim3(OUTPUT_DIM / 128, NUM_CELLS / 128, SPLITK), 256>>>();
    reduce_out_kernel<<<(NUM_CELLS * OUTPUT_DIM + 255) / 256, 256>>>(pbfinal, out);
}